// round 15
// baseline (speedup 1.0000x reference)
#include <cuda_runtime.h>
#include <math.h>
#include <stdint.h>

#define MAXN 8192
#define MAXM 1024          // max valid boxes (E[M]~800, sigma~27; 8+ sigma headroom)
#define W    16            // 64-bit words per suppression row (MAXM/64)

typedef unsigned long long u64;

__device__ float4 g_boxes[MAXN];
__device__ u64 g_keys[MAXM];     // compacted valid keys (unsorted)
__device__ u64 g_skeys[MAXM];    // sorted keys
__device__ float4 g_sboxes[MAXM];
__device__ u64 g_sup[MAXM * W];  // suppression bit matrix (upper triangular)
__device__ u64 g_allOR[W];       // OR of all rows (cols with a suppressor)
__device__ u64 g_rowNZ[W];       // rows with any nonzero word
__device__ int g_count, g_c1;    // valid count + prep done-counter (k_scan resets)

// ---------------------------------------------------------------------------
// Kernel A: per-box prep with BLOCK-AGGREGATED compaction (1 global atomic
// per block instead of ~800 same-address RMWs) + bitonic sort (last block).
// ---------------------------------------------------------------------------
__global__ void __launch_bounds__(1024, 1)
k_prep_sort(const float* __restrict__ o0, const float* __restrict__ o1,
            int P0, int P1, float* __restrict__ out, int out_size, int N) {
    const int tid = threadIdx.x;
    __shared__ int blkCount, blkBase;
    if (tid == 0) blkCount = 0;
    __syncthreads();

    int n = blockIdx.x * 1024 + tid;
    int stride = gridDim.x * 1024;
    for (int t = n; t < out_size; t += stride) out[t] = 0.0f;

    bool m = false;
    int lpos = 0;
    u64 key = 0;

    if (n < N) {
        const float* src;
        int P, loc;
        int A0 = P0 * P0;
        if (n < A0) { src = o0; P = P0; loc = n; }
        else        { src = o1; P = P1; loc = n - A0; }
        int i = loc / P, j = loc - i * P;
        int A = P * P;

        float prob = src[0 * A + loc];
        float x1   = src[1 * A + loc];
        float x2   = src[2 * A + loc];
        float x3   = src[3 * A + loc];
        float x4   = src[4 * A + loc];

        float xps = 640.0f / (float)P;   // exact: 16 or 8
        float yps = 480.0f / (float)P;   // exact: 12 or 6
        m = prob > 0.9f;

        float c1 = m ? (x1 * xps + (float)i * xps) : x1;
        float c2 = m ? (x2 * yps + (float)j * yps) : x2;
        float c3 = m ? (x3 * 640.0f) : x3;
        float c4 = m ? (x4 * 480.0f) : x4;

        float X1 = rintf(c1);
        float Y1 = rintf(c2);
        float X2 = rintf(c3 + c1);
        float Y2 = rintf(c4 + c2);

        g_boxes[n] = make_float4(X1, Y1, X2, Y2);

        if (m) {
            lpos = atomicAdd(&blkCount, 1);   // shared: fast, parallel per SM
            unsigned int hi = 0xFFFFFFFFu - __float_as_uint(prob); // desc score
            key = ((u64)hi << 32) | (unsigned int)n;               // tie: asc idx
        }
    }
    __syncthreads();
    if (tid == 0) blkBase = atomicAdd(&g_count, blkCount);  // 1 global RMW/block
    __syncthreads();

    if (m) {
        int pos = blkBase + lpos;
        if (pos < MAXM) g_keys[pos] = key;
    }

    // Last-block election (release: every thread fences its own stores).
    __threadfence();
    __syncthreads();
    __shared__ int flag;
    if (tid == 0) flag = (atomicAdd(&g_c1, 1) == (int)gridDim.x - 1);
    __syncthreads();
    if (!flag) return;

    // ---- hybrid bitonic sort (last block, P2=1024 with padding) ----
    int M = g_count; if (M > MAXM) M = MAXM;
    __shared__ u64 keys[MAXM];

    u64 v = (tid < M) ? __ldcg(&g_keys[tid]) : 0xFFFFFFFFFFFFFFFFull;

#pragma unroll
    for (int k = 2; k <= 32; k <<= 1) {
#pragma unroll
        for (int j = k >> 1; j >= 1; j >>= 1) {
            u64 p = __shfl_xor_sync(0xFFFFFFFFu, v, j);
            bool up = ((tid & k) == 0);
            bool keepmin = (((tid & j) == 0) == up);
            u64 lo = v < p ? v : p;
            u64 hi = v < p ? p : v;
            v = keepmin ? lo : hi;
        }
    }
    keys[tid] = v;
    __syncthreads();

    for (int k = 64; k <= 1024; k <<= 1) {
        for (int j = k >> 1; j >= 32; j >>= 1) {
            int ixj = tid ^ j;
            if (ixj > tid) {
                u64 a = keys[tid], b = keys[ixj];
                bool up = ((tid & k) == 0);
                if ((a > b) == up) { keys[tid] = b; keys[ixj] = a; }
            }
            __syncthreads();
        }
        v = keys[tid];
        bool up = ((tid & k) == 0);
#pragma unroll
        for (int j = 16; j >= 1; j >>= 1) {
            u64 p = __shfl_xor_sync(0xFFFFFFFFu, v, j);
            bool keepmin = (((tid & j) == 0) == up);
            u64 lo = v < p ? v : p;
            u64 hi = v < p ? p : v;
            v = keepmin ? lo : hi;
        }
        keys[tid] = v;
        __syncthreads();
    }

    if (tid < M) {
        u64 kk = keys[tid];
        g_skeys[tid] = kk;
        g_sboxes[tid] = g_boxes[(unsigned int)(kk & 0xFFFFFFFFu)];
    }
}

// ---------------------------------------------------------------------------
// K3: suppression bit matrix (upper triangular) + allOR/rowNZ summaries.
// Exact iou>0.5 via inter > 0.5*uni (all quantities integer-valued fp32).
// ---------------------------------------------------------------------------
__global__ void k_matrix() {
    int M = g_count; if (M > MAXM) M = MAXM;
    int t = blockIdx.x * blockDim.x + threadIdx.x;
    int i  = t >> 4;       // row
    int jw = t & (W - 1);  // word within row
    if (i >= M) return;

    int jbase = jw << 6;
    u64 word = 0;
    if (jbase + 64 > i + 1 && jbase < M) {
        float4 bi = g_sboxes[i];
        float ai = (bi.z - bi.x) * (bi.w - bi.y);
        int jend = min(jbase + 64, M);
        for (int j = max(jbase, i + 1); j < jend; ++j) {
            float4 bj = g_sboxes[j];
            float iw = fminf(bi.z, bj.z) - fmaxf(bi.x, bj.x);
            float ih = fminf(bi.w, bj.w) - fmaxf(bi.y, bj.y);
            iw = fmaxf(iw, 0.0f);
            ih = fmaxf(ih, 0.0f);
            float inter = iw * ih;
            float aj = (bj.z - bj.x) * (bj.w - bj.y);
            float uni = ai + aj - inter;
            if (uni > 0.0f && inter > 0.5f * uni)
                word |= 1ull << (j - jbase);
        }
    }
    g_sup[t] = word;
    if (word) {
        atomicOr(&g_allOR[jw], word);
        atomicOr(&g_rowNZ[i >> 6], 1ull << (i & 63));
    }
}

// ---------------------------------------------------------------------------
// K4 (R11 champion, frozen): sparse gather of nonzero rows + preOR; serial
// loop over suppressible suppressors; broadcast-LDS critical path.
// Emit kept rows; reset all state for next graph replay.
// ---------------------------------------------------------------------------
extern __shared__ u64 sup_s[];  // MAXM*W u64 = 128KB (only nonzero rows written)
__global__ void __launch_bounds__(1024, 1) k_scan(float* __restrict__ out) {
    __shared__ u64 allOR_s[W], rowNZ_s[W], preOR_s[W], rem_s[W];
    const int tid = threadIdx.x;
    const int bd  = 1024;

    int M = g_count; if (M > MAXM) M = MAXM;

    if (tid < W) {
        allOR_s[tid] = g_allOR[tid];
        rowNZ_s[tid] = g_rowNZ[tid];
        preOR_s[tid] = 0;
    }
    __syncthreads();

    // Gather ONLY nonzero rows into smem; fold preOR = OR of rows of
    // definitely-kept boxes (column bit not in allOR).
    u64 myPre = 0;
    int tot = M * W;
    for (int q = tid; q < tot; q += bd) {
        int ri = q >> 4;
        if ((rowNZ_s[ri >> 6] >> (ri & 63)) & 1ull) {
            u64 vv = g_sup[q];
            sup_s[q] = vv;
            if (!((allOR_s[ri >> 6] >> (ri & 63)) & 1ull)) myPre |= vv;
        }
    }
    myPre |= __shfl_xor_sync(0xFFFFFFFFu, myPre, 16);
    if ((tid & 31) < 16) atomicOr(&preOR_s[tid & 15], myPre);
    __syncthreads();

    // Serial warp loop over suppressible suppressors.
    if (tid < 32) {
        const int lane = tid;
        const int lw   = lane & 15;
        u64 rem_own = (lane < W) ? preOR_s[lane] : 0;
        int nwords = (M + 63) >> 6;

        for (int w = 0; w < nwords; ++w) {
            u64 remw = __shfl_sync(0xFFFFFFFFu, rem_own, w);
            u64 cand = allOR_s[w] & rowNZ_s[w] & ~remw;
            unsigned wordbase = (unsigned)w << 10;   // (w*64) << 4
            while (cand) {
                int b = __ffsll((long long)cand) - 1;
                unsigned rowbase = wordbase + ((unsigned)b << 4);
                u64 bc = sup_s[rowbase + w];     // broadcast LDS: ON the chain
                u64 rv = sup_s[rowbase + lw];    // per-lane word: OFF the chain
                rem_own |= (lane < W) ? rv : 0;
                cand = (cand & (cand - 1)) & ~bc;
            }
        }
        if (lane < W) rem_s[lane] = rem_own;
    }
    __syncthreads();

    // Emit kept rows: [score, x1, y1, x2-x1, y2-y1]; rest already zero.
    for (int s = tid; s < M; s += bd) {
        if (!((rem_s[s >> 6] >> (s & 63)) & 1ull)) {
            u64 kk = g_skeys[s];
            float score = __uint_as_float(0xFFFFFFFFu - (unsigned int)(kk >> 32));
            float4 b = g_sboxes[s];
            float* o = out + 5 * s;
            o[0] = score;
            o[1] = b.x;
            o[2] = b.y;
            o[3] = b.z - b.x;
            o[4] = b.w - b.y;
        }
    }

    // Reset all cross-launch state for the next graph replay.
    if (tid < W) { g_allOR[tid] = 0; g_rowNZ[tid] = 0; }
    if (tid == 0) { g_count = 0; g_c1 = 0; }
}

extern "C" void kernel_launch(void* const* d_in, const int* in_sizes, int n_in,
                              void* d_out, int out_size) {
    const float* o0 = (const float*)d_in[0];
    const float* o1 = (const float*)d_in[1];
    int P0 = (int)lround(sqrt((double)in_sizes[0] / 5.0));
    int P1 = (int)lround(sqrt((double)in_sizes[1] / 5.0));
    int N = P0 * P0 + P1 * P1;
    float* out = (float*)d_out;

    static int smem_set = 0;
    if (!smem_set) {
        cudaFuncSetAttribute(k_scan, cudaFuncAttributeMaxDynamicSharedMemorySize,
                             MAXM * W * (int)sizeof(u64));
        smem_set = 1;
    }

    int blocksA = (N + 1023) / 1024;                 // 8
    k_prep_sort<<<blocksA, 1024>>>(o0, o1, P0, P1, out, out_size, N);
    k_matrix<<<(MAXM * W) / 256, 256>>>();
    k_scan<<<1, 1024, MAXM * W * (int)sizeof(u64)>>>(out);
}

// round 16
// speedup vs baseline: 1.0645x; 1.0645x over previous
#include <cuda_runtime.h>
#include <math.h>
#include <stdint.h>

#define MAXN 8192
#define MAXM 1024          // max valid boxes (E[M]~800, sigma~27; 8+ sigma headroom)
#define W    16            // 64-bit words per suppression row (MAXM/64)

typedef unsigned long long u64;

__device__ float4 g_boxes[MAXN];
__device__ u64 g_keys[MAXM];     // compacted valid keys (unsorted)
__device__ u64 g_skeys[MAXM];    // sorted keys
__device__ float4 g_sboxes[MAXM];
__device__ u64 g_sup[MAXM * W];  // suppression bit matrix (upper triangular)
__device__ u64 g_allOR[W];       // OR of all rows (cols with a suppressor)
__device__ u64 g_rowNZ[W];       // rows with any nonzero word
__device__ int g_count, g_c1;    // valid count + prep done-counter (k_scan resets)

// ---------------------------------------------------------------------------
// Kernel A (R13 champion): per-box prep (all blocks) + bitonic sort (last).
// ---------------------------------------------------------------------------
__global__ void __launch_bounds__(1024, 1)
k_prep_sort(const float* __restrict__ o0, const float* __restrict__ o1,
            int P0, int P1, float* __restrict__ out, int out_size, int N) {
    const int tid = threadIdx.x;
    int n = blockIdx.x * 1024 + tid;
    int stride = gridDim.x * 1024;
    for (int t = n; t < out_size; t += stride) out[t] = 0.0f;

    if (n < N) {
        const float* src;
        int P, loc;
        int A0 = P0 * P0;
        if (n < A0) { src = o0; P = P0; loc = n; }
        else        { src = o1; P = P1; loc = n - A0; }
        int i = loc / P, j = loc - i * P;
        int A = P * P;

        float prob = src[0 * A + loc];
        float x1   = src[1 * A + loc];
        float x2   = src[2 * A + loc];
        float x3   = src[3 * A + loc];
        float x4   = src[4 * A + loc];

        float xps = 640.0f / (float)P;   // exact: 16 or 8
        float yps = 480.0f / (float)P;   // exact: 12 or 6
        bool m = prob > 0.9f;

        float c1 = m ? (x1 * xps + (float)i * xps) : x1;
        float c2 = m ? (x2 * yps + (float)j * yps) : x2;
        float c3 = m ? (x3 * 640.0f) : x3;
        float c4 = m ? (x4 * 480.0f) : x4;

        float X1 = rintf(c1);
        float Y1 = rintf(c2);
        float X2 = rintf(c3 + c1);
        float Y2 = rintf(c4 + c2);

        g_boxes[n] = make_float4(X1, Y1, X2, Y2);

        if (m) {
            int pos = atomicAdd(&g_count, 1);
            if (pos < MAXM) {
                unsigned int hi = 0xFFFFFFFFu - __float_as_uint(prob); // desc score
                g_keys[pos] = ((u64)hi << 32) | (unsigned int)n;       // tie: asc idx
            }
        }
    }

    // Last-block election (release: every thread fences its own stores).
    __threadfence();
    __syncthreads();
    __shared__ int flag;
    if (tid == 0) flag = (atomicAdd(&g_c1, 1) == (int)gridDim.x - 1);
    __syncthreads();
    if (!flag) return;

    // ---- hybrid bitonic sort (last block, P2=1024 with padding) ----
    int M = g_count; if (M > MAXM) M = MAXM;
    __shared__ u64 keys[MAXM];

    u64 v = (tid < M) ? __ldcg(&g_keys[tid]) : 0xFFFFFFFFFFFFFFFFull;

#pragma unroll
    for (int k = 2; k <= 32; k <<= 1) {
#pragma unroll
        for (int j = k >> 1; j >= 1; j >>= 1) {
            u64 p = __shfl_xor_sync(0xFFFFFFFFu, v, j);
            bool up = ((tid & k) == 0);
            bool keepmin = (((tid & j) == 0) == up);
            u64 lo = v < p ? v : p;
            u64 hi = v < p ? p : v;
            v = keepmin ? lo : hi;
        }
    }
    keys[tid] = v;
    __syncthreads();

    for (int k = 64; k <= 1024; k <<= 1) {
        for (int j = k >> 1; j >= 32; j >>= 1) {
            int ixj = tid ^ j;
            if (ixj > tid) {
                u64 a = keys[tid], b = keys[ixj];
                bool up = ((tid & k) == 0);
                if ((a > b) == up) { keys[tid] = b; keys[ixj] = a; }
            }
            __syncthreads();
        }
        v = keys[tid];
        bool up = ((tid & k) == 0);
#pragma unroll
        for (int j = 16; j >= 1; j >>= 1) {
            u64 p = __shfl_xor_sync(0xFFFFFFFFu, v, j);
            bool keepmin = (((tid & j) == 0) == up);
            u64 lo = v < p ? v : p;
            u64 hi = v < p ? p : v;
            v = keepmin ? lo : hi;
        }
        keys[tid] = v;
        __syncthreads();
    }

    if (tid < M) {
        u64 kk = keys[tid];
        g_skeys[tid] = kk;
        g_sboxes[tid] = g_boxes[(unsigned int)(kk & 0xFFFFFFFFu)];
    }
}

// ---------------------------------------------------------------------------
// K3: suppression bit matrix (upper triangular) + allOR/rowNZ summaries.
// Exact iou>0.5 via inter > 0.5*uni (all quantities integer-valued fp32).
// ---------------------------------------------------------------------------
__global__ void k_matrix() {
    int M = g_count; if (M > MAXM) M = MAXM;
    int t = blockIdx.x * blockDim.x + threadIdx.x;
    int i  = t >> 4;       // row
    int jw = t & (W - 1);  // word within row
    if (i >= M) return;

    int jbase = jw << 6;
    u64 word = 0;
    if (jbase + 64 > i + 1 && jbase < M) {
        float4 bi = g_sboxes[i];
        float ai = (bi.z - bi.x) * (bi.w - bi.y);
        int jend = min(jbase + 64, M);
        for (int j = max(jbase, i + 1); j < jend; ++j) {
            float4 bj = g_sboxes[j];
            float iw = fminf(bi.z, bj.z) - fmaxf(bi.x, bj.x);
            float ih = fminf(bi.w, bj.w) - fmaxf(bi.y, bj.y);
            iw = fmaxf(iw, 0.0f);
            ih = fmaxf(ih, 0.0f);
            float inter = iw * ih;
            float aj = (bj.z - bj.x) * (bj.w - bj.y);
            float uni = ai + aj - inter;
            if (uni > 0.0f && inter > 0.5f * uni)
                word |= 1ull << (j - jbase);
        }
    }
    g_sup[t] = word;
    if (word) {
        atomicOr(&g_allOR[jw], word);
        atomicOr(&g_rowNZ[i >> 6], 1ull << (i & 63));
    }
}

// ---------------------------------------------------------------------------
// K4: sparse gather (+ diagonal-block array) + preOR; per-word FAST PATH:
// if no cand-kills-cand within the word (inKill==0, via register-resident
// diagonal + redux), ALL cand bits are kept -> parallel row-OR, no serial
// walk. Slow path (rare): exact R11 serial loop for that word.
// Emit kept rows; reset state for next replay.
// ---------------------------------------------------------------------------
extern __shared__ u64 sup_s[];  // MAXM*W u64 = 128KB (only nonzero rows written)
__global__ void __launch_bounds__(1024, 1) k_scan(float* __restrict__ out) {
    __shared__ u64 allOR_s[W], rowNZ_s[W], preOR_s[W], rem_s[W];
    __shared__ u64 diag_s[W * 64];   // diag_s[w*64+b] = sup[row base+b, word w]
    const int tid = threadIdx.x;
    const int bd  = 1024;

    int M = g_count; if (M > MAXM) M = MAXM;

    if (tid < W) {
        allOR_s[tid] = g_allOR[tid];
        rowNZ_s[tid] = g_rowNZ[tid];
        preOR_s[tid] = 0;
    }
    diag_s[tid] = 0;                 // 16*64 == 1024 == blockDim
    __syncthreads();

    // Gather ONLY nonzero rows into smem (+ diagonal copies); fold preOR.
    u64 myPre = 0;
    int tot = M * W;
    for (int q = tid; q < tot; q += bd) {
        int ri = q >> 4;
        if ((rowNZ_s[ri >> 6] >> (ri & 63)) & 1ull) {
            u64 vv = g_sup[q];
            sup_s[q] = vv;
            if ((q & 15) == (ri >> 6))                    // diagonal word
                diag_s[((q & 15) << 6) + (ri & 63)] = vv;
            if (!((allOR_s[ri >> 6] >> (ri & 63)) & 1ull)) myPre |= vv;
        }
    }
    myPre |= __shfl_xor_sync(0xFFFFFFFFu, myPre, 16);
    if ((tid & 31) < 16) atomicOr(&preOR_s[tid & 15], myPre);
    __syncthreads();

    // Warp loop over words; fast path when no within-word cand-on-cand kills.
    if (tid < 32) {
        const int lane = tid;
        const int lw   = lane & 15;
        const bool hiHalf = lane >= 16;
        u64 rem_own = hiHalf ? 0ull : preOR_s[lw];
        int nwords = (M + 63) >> 6;

        for (int w = 0; w < nwords; ++w) {
            u64 remw = __shfl_sync(0xFFFFFFFFu, rem_own, w)
                     | __shfl_sync(0xFFFFFFFFu, rem_own, 16 + w);
            u64 cand = allOR_s[w] & rowNZ_s[w] & ~remw;
            if (!cand) continue;
            unsigned wordbase = (unsigned)w << 10;       // (w*64) << 4

            // Register-resident diagonal: lane holds rows (lane) and (32+lane).
            u64 D0 = diag_s[(w << 6) + lane];
            u64 D1 = diag_s[(w << 6) + 32 + lane];
            u64 contrib = (((cand >> lane) & 1ull) ? D0 : 0ull)
                        | (((cand >> (32 + lane)) & 1ull) ? D1 : 0ull);
            contrib &= cand;                             // victims among cand
            unsigned iklo = __reduce_or_sync(0xFFFFFFFFu, (unsigned)contrib);
            unsigned ikhi = __reduce_or_sync(0xFFFFFFFFu, (unsigned)(contrib >> 32));

            if ((iklo | ikhi) == 0u) {
                // FAST PATH: every cand bit is kept. Row-OR 2 rows/iter.
                u64 c = cand;
                while (c) {
                    int b0 = __ffsll((long long)c) - 1;
                    u64 c2 = c & (c - 1);
                    int b1 = c2 ? (__ffsll((long long)c2) - 1) : b0;
                    int rb = hiHalf ? b1 : b0;           // dup when odd: idempotent
                    rem_own |= sup_s[wordbase + ((unsigned)rb << 4) + lw];
                    c = c2 & (c2 - 1);
                }
            } else {
                // SLOW PATH: exact serial greedy for this word (R11 loop).
                u64 c = cand;
                while (c) {
                    int b = __ffsll((long long)c) - 1;
                    unsigned rowbase = wordbase + ((unsigned)b << 4);
                    u64 bc = diag_s[(w << 6) + b];       // diagonal word
                    u64 rv = sup_s[rowbase + lw];
                    if (!hiHalf) rem_own |= rv;
                    c = (c & (c - 1)) & ~bc;
                }
            }
        }
        rem_own |= __shfl_xor_sync(0xFFFFFFFFu, rem_own, 16);
        if (lane < W) rem_s[lane] = rem_own;
    }
    __syncthreads();

    // Emit kept rows: [score, x1, y1, x2-x1, y2-y1]; rest already zero.
    for (int s = tid; s < M; s += bd) {
        if (!((rem_s[s >> 6] >> (s & 63)) & 1ull)) {
            u64 kk = g_skeys[s];
            float score = __uint_as_float(0xFFFFFFFFu - (unsigned int)(kk >> 32));
            float4 b = g_sboxes[s];
            float* o = out + 5 * s;
            o[0] = score;
            o[1] = b.x;
            o[2] = b.y;
            o[3] = b.z - b.x;
            o[4] = b.w - b.y;
        }
    }

    // Reset all cross-launch state for the next graph replay.
    if (tid < W) { g_allOR[tid] = 0; g_rowNZ[tid] = 0; }
    if (tid == 0) { g_count = 0; g_c1 = 0; }
}

extern "C" void kernel_launch(void* const* d_in, const int* in_sizes, int n_in,
                              void* d_out, int out_size) {
    const float* o0 = (const float*)d_in[0];
    const float* o1 = (const float*)d_in[1];
    int P0 = (int)lround(sqrt((double)in_sizes[0] / 5.0));
    int P1 = (int)lround(sqrt((double)in_sizes[1] / 5.0));
    int N = P0 * P0 + P1 * P1;
    float* out = (float*)d_out;

    static int smem_set = 0;
    if (!smem_set) {
        cudaFuncSetAttribute(k_scan, cudaFuncAttributeMaxDynamicSharedMemorySize,
                             MAXM * W * (int)sizeof(u64));
        smem_set = 1;
    }

    int blocksA = (N + 1023) / 1024;                 // 8
    k_prep_sort<<<blocksA, 1024>>>(o0, o1, P0, P1, out, out_size, N);
    k_matrix<<<(MAXM * W) / 256, 256>>>();
    k_scan<<<1, 1024, MAXM * W * (int)sizeof(u64)>>>(out);
}

// round 17
// speedup vs baseline: 1.1393x; 1.0702x over previous
#include <cuda_runtime.h>
#include <math.h>
#include <stdint.h>

#define MAXN 8192
#define MAXM 1024          // max valid boxes (E[M]~800, sigma~27; 8+ sigma headroom)
#define W    16            // 64-bit words per suppression row (MAXM/64)

typedef unsigned long long u64;

__device__ float4 g_boxes[MAXN];
__device__ u64 g_keys[MAXM];     // compacted valid keys (unsorted)
__device__ u64 g_skeys[MAXM];    // sorted keys
__device__ float4 g_sboxes[MAXM];
__device__ u64 g_sup[MAXM * W];  // suppression bit matrix (upper triangular)
__device__ u64 g_allOR[W];       // OR of all rows (cols with a suppressor)
__device__ u64 g_rowNZ[W];       // rows with any nonzero word
__device__ int g_count, g_c1;    // valid count + prep done-counter (k_scan resets)

// ---------------------------------------------------------------------------
// Kernel A (R13 champion): per-box prep (all blocks) + bitonic sort (last).
// ---------------------------------------------------------------------------
__global__ void __launch_bounds__(1024, 1)
k_prep_sort(const float* __restrict__ o0, const float* __restrict__ o1,
            int P0, int P1, float* __restrict__ out, int out_size, int N) {
    const int tid = threadIdx.x;
    int n = blockIdx.x * 1024 + tid;
    int stride = gridDim.x * 1024;
    for (int t = n; t < out_size; t += stride) out[t] = 0.0f;

    if (n < N) {
        const float* src;
        int P, loc;
        int A0 = P0 * P0;
        if (n < A0) { src = o0; P = P0; loc = n; }
        else        { src = o1; P = P1; loc = n - A0; }
        int i = loc / P, j = loc - i * P;
        int A = P * P;

        float prob = src[0 * A + loc];
        float x1   = src[1 * A + loc];
        float x2   = src[2 * A + loc];
        float x3   = src[3 * A + loc];
        float x4   = src[4 * A + loc];

        float xps = 640.0f / (float)P;   // exact: 16 or 8
        float yps = 480.0f / (float)P;   // exact: 12 or 6
        bool m = prob > 0.9f;

        float c1 = m ? (x1 * xps + (float)i * xps) : x1;
        float c2 = m ? (x2 * yps + (float)j * yps) : x2;
        float c3 = m ? (x3 * 640.0f) : x3;
        float c4 = m ? (x4 * 480.0f) : x4;

        float X1 = rintf(c1);
        float Y1 = rintf(c2);
        float X2 = rintf(c3 + c1);
        float Y2 = rintf(c4 + c2);

        g_boxes[n] = make_float4(X1, Y1, X2, Y2);

        if (m) {
            int pos = atomicAdd(&g_count, 1);
            if (pos < MAXM) {
                unsigned int hi = 0xFFFFFFFFu - __float_as_uint(prob); // desc score
                g_keys[pos] = ((u64)hi << 32) | (unsigned int)n;       // tie: asc idx
            }
        }
    }

    // Last-block election (release: every thread fences its own stores).
    __threadfence();
    __syncthreads();
    __shared__ int flag;
    if (tid == 0) flag = (atomicAdd(&g_c1, 1) == (int)gridDim.x - 1);
    __syncthreads();
    if (!flag) return;

    // ---- hybrid bitonic sort (last block, P2=1024 with padding) ----
    int M = g_count; if (M > MAXM) M = MAXM;
    __shared__ u64 keys[MAXM];

    u64 v = (tid < M) ? __ldcg(&g_keys[tid]) : 0xFFFFFFFFFFFFFFFFull;

#pragma unroll
    for (int k = 2; k <= 32; k <<= 1) {
#pragma unroll
        for (int j = k >> 1; j >= 1; j >>= 1) {
            u64 p = __shfl_xor_sync(0xFFFFFFFFu, v, j);
            bool up = ((tid & k) == 0);
            bool keepmin = (((tid & j) == 0) == up);
            u64 lo = v < p ? v : p;
            u64 hi = v < p ? p : v;
            v = keepmin ? lo : hi;
        }
    }
    keys[tid] = v;
    __syncthreads();

    for (int k = 64; k <= 1024; k <<= 1) {
        for (int j = k >> 1; j >= 32; j >>= 1) {
            int ixj = tid ^ j;
            if (ixj > tid) {
                u64 a = keys[tid], b = keys[ixj];
                bool up = ((tid & k) == 0);
                if ((a > b) == up) { keys[tid] = b; keys[ixj] = a; }
            }
            __syncthreads();
        }
        v = keys[tid];
        bool up = ((tid & k) == 0);
#pragma unroll
        for (int j = 16; j >= 1; j >>= 1) {
            u64 p = __shfl_xor_sync(0xFFFFFFFFu, v, j);
            bool keepmin = (((tid & j) == 0) == up);
            u64 lo = v < p ? v : p;
            u64 hi = v < p ? p : v;
            v = keepmin ? lo : hi;
        }
        keys[tid] = v;
        __syncthreads();
    }

    if (tid < M) {
        u64 kk = keys[tid];
        g_skeys[tid] = kk;
        g_sboxes[tid] = g_boxes[(unsigned int)(kk & 0xFFFFFFFFu)];
    }
}

// ---------------------------------------------------------------------------
// K3: suppression bit matrix (upper triangular) + allOR/rowNZ summaries.
// Exact iou>0.5 via inter > 0.5*uni (all quantities integer-valued fp32).
// ---------------------------------------------------------------------------
__global__ void k_matrix() {
    int M = g_count; if (M > MAXM) M = MAXM;
    int t = blockIdx.x * blockDim.x + threadIdx.x;
    int i  = t >> 4;       // row
    int jw = t & (W - 1);  // word within row
    if (i >= M) return;

    int jbase = jw << 6;
    u64 word = 0;
    if (jbase + 64 > i + 1 && jbase < M) {
        float4 bi = g_sboxes[i];
        float ai = (bi.z - bi.x) * (bi.w - bi.y);
        int jend = min(jbase + 64, M);
        for (int j = max(jbase, i + 1); j < jend; ++j) {
            float4 bj = g_sboxes[j];
            float iw = fminf(bi.z, bj.z) - fmaxf(bi.x, bj.x);
            float ih = fminf(bi.w, bj.w) - fmaxf(bi.y, bj.y);
            iw = fmaxf(iw, 0.0f);
            ih = fmaxf(ih, 0.0f);
            float inter = iw * ih;
            float aj = (bj.z - bj.x) * (bj.w - bj.y);
            float uni = ai + aj - inter;
            if (uni > 0.0f && inter > 0.5f * uni)
                word |= 1ull << (j - jbase);
        }
    }
    g_sup[t] = word;
    if (word) {
        atomicOr(&g_allOR[jw], word);
        atomicOr(&g_rowNZ[i >> 6], 1ull << (i & 63));
    }
}

// ---------------------------------------------------------------------------
// K4: 4-way BATCHED gather (4 LDGs in flight before stores — shortens the
// LDG->STS dependency chain 13 rounds -> 4) + preOR; R11 serial loop
// (exonerated, frozen); emit with PREFETCHED keys/boxes (loads issued before
// the serial-phase barrier). Reset state for next replay.
// ---------------------------------------------------------------------------
extern __shared__ u64 sup_s[];  // MAXM*W u64 = 128KB (only nonzero rows written)
__global__ void __launch_bounds__(1024, 1) k_scan(float* __restrict__ out) {
    __shared__ u64 allOR_s[W], rowNZ_s[W], preOR_s[W], rem_s[W];
    const int tid = threadIdx.x;

    int M = g_count; if (M > MAXM) M = MAXM;

    if (tid < W) {
        allOR_s[tid] = g_allOR[tid];
        rowNZ_s[tid] = g_rowNZ[tid];
        preOR_s[tid] = 0;
    }
    __syncthreads();

    // Batched gather of nonzero rows + preOR fold.
    // Stride 4096 ≡ 0 mod 16 keeps each thread on word index tid&15.
    u64 myPre = 0;
    int tot = M * W;
    for (int q = tid; q < tot; q += 4096) {
        int q1 = q + 1024, q2 = q + 2048, q3 = q + 3072;
        int r0 = q >> 4, r1 = q1 >> 4, r2 = q2 >> 4, r3 = q3 >> 4;
        bool p0 = (rowNZ_s[r0 >> 6] >> (r0 & 63)) & 1ull;
        bool p1 = (q1 < tot) && ((rowNZ_s[r1 >> 6] >> (r1 & 63)) & 1ull);
        bool p2 = (q2 < tot) && ((rowNZ_s[r2 >> 6] >> (r2 & 63)) & 1ull);
        bool p3 = (q3 < tot) && ((rowNZ_s[r3 >> 6] >> (r3 & 63)) & 1ull);
        u64 v0 = p0 ? g_sup[q]  : 0ull;      // 4 independent LDGs in flight
        u64 v1 = p1 ? g_sup[q1] : 0ull;
        u64 v2 = p2 ? g_sup[q2] : 0ull;
        u64 v3 = p3 ? g_sup[q3] : 0ull;
        if (p0) { sup_s[q]  = v0; if (!((allOR_s[r0 >> 6] >> (r0 & 63)) & 1ull)) myPre |= v0; }
        if (p1) { sup_s[q1] = v1; if (!((allOR_s[r1 >> 6] >> (r1 & 63)) & 1ull)) myPre |= v1; }
        if (p2) { sup_s[q2] = v2; if (!((allOR_s[r2 >> 6] >> (r2 & 63)) & 1ull)) myPre |= v2; }
        if (p3) { sup_s[q3] = v3; if (!((allOR_s[r3 >> 6] >> (r3 & 63)) & 1ull)) myPre |= v3; }
    }
    myPre |= __shfl_xor_sync(0xFFFFFFFFu, myPre, 16);
    if ((tid & 31) < 16) atomicOr(&preOR_s[tid & 15], myPre);
    __syncthreads();

    // Emit prefetch: issue global loads now; consumed after the barrier.
    u64 kk = 0; float4 bx = make_float4(0.f, 0.f, 0.f, 0.f);
    if (tid < M) { kk = g_skeys[tid]; bx = g_sboxes[tid]; }

    // Serial warp loop over suppressible suppressors (R11, frozen).
    if (tid < 32) {
        const int lane = tid;
        const int lw   = lane & 15;
        u64 rem_own = (lane < W) ? preOR_s[lane] : 0;
        int nwords = (M + 63) >> 6;

        for (int w = 0; w < nwords; ++w) {
            u64 remw = __shfl_sync(0xFFFFFFFFu, rem_own, w);
            u64 cand = allOR_s[w] & rowNZ_s[w] & ~remw;
            unsigned wordbase = (unsigned)w << 10;   // (w*64) << 4
            while (cand) {
                int b = __ffsll((long long)cand) - 1;
                unsigned rowbase = wordbase + ((unsigned)b << 4);
                u64 bc = sup_s[rowbase + w];     // broadcast LDS: ON the chain
                u64 rv = sup_s[rowbase + lw];    // per-lane word: OFF the chain
                rem_own |= (lane < W) ? rv : 0;
                cand = (cand & (cand - 1)) & ~bc;
            }
        }
        if (lane < W) rem_s[lane] = rem_own;
    }
    __syncthreads();

    // Emit kept rows from prefetched registers (M <= blockDim).
    if (tid < M && !((rem_s[tid >> 6] >> (tid & 63)) & 1ull)) {
        float score = __uint_as_float(0xFFFFFFFFu - (unsigned int)(kk >> 32));
        float* o = out + 5 * tid;
        o[0] = score;
        o[1] = bx.x;
        o[2] = bx.y;
        o[3] = bx.z - bx.x;
        o[4] = bx.w - bx.y;
    }

    // Reset all cross-launch state for the next graph replay.
    if (tid < W) { g_allOR[tid] = 0; g_rowNZ[tid] = 0; }
    if (tid == 0) { g_count = 0; g_c1 = 0; }
}

extern "C" void kernel_launch(void* const* d_in, const int* in_sizes, int n_in,
                              void* d_out, int out_size) {
    const float* o0 = (const float*)d_in[0];
    const float* o1 = (const float*)d_in[1];
    int P0 = (int)lround(sqrt((double)in_sizes[0] / 5.0));
    int P1 = (int)lround(sqrt((double)in_sizes[1] / 5.0));
    int N = P0 * P0 + P1 * P1;
    float* out = (float*)d_out;

    static int smem_set = 0;
    if (!smem_set) {
        cudaFuncSetAttribute(k_scan, cudaFuncAttributeMaxDynamicSharedMemorySize,
                             MAXM * W * (int)sizeof(u64));
        smem_set = 1;
    }

    int blocksA = (N + 1023) / 1024;                 // 8
    k_prep_sort<<<blocksA, 1024>>>(o0, o1, P0, P1, out, out_size, N);
    k_matrix<<<(MAXM * W) / 256, 256>>>();
    k_scan<<<1, 1024, MAXM * W * (int)sizeof(u64)>>>(out);
}